// round 4
// baseline (speedup 1.0000x reference)
#include <cuda_runtime.h>
#include <cstdint>

#define VOCAB 50257
#define BATCH 4096

// Scratch for per-row losses + completion counter (no device mallocs).
__device__ float g_row_loss[BATCH];
__device__ unsigned int g_done = 0;   // self-resetting each launch

__global__ __launch_bounds__(256, 4) void ce_fused_kernel(
    const float* __restrict__ pred,
    const int* __restrict__ y,       // JAX x64-disabled => int32 labels
    float* __restrict__ out)
{
    const int row = blockIdx.x;
    const float* __restrict__ p = pred + (size_t)row * VOCAB;
    const int tid = threadIdx.x;
    const int T = 256;

    // Row base misalignment (in floats) relative to 16B; prologue to align.
    const int mis = (int)(((uintptr_t)p & 15u) >> 2);
    const int pro = (4 - mis) & 3;

    float s0 = 0.f, s1 = 0.f, s2 = 0.f, s3 = 0.f;

    if (tid < pro) s0 += __expf(p[tid]);

    const float4* __restrict__ p4 = (const float4*)(p + pro);
    const int n4 = (VOCAB - pro) >> 2;

    // Main loop: 8 front-batched streaming LDG.128 (MLP=8/thread), then 32 EX2.
    int i = tid;
    for (; i + 7 * T < n4; i += 8 * T) {
        float4 v[8];
        #pragma unroll
        for (int u = 0; u < 8; u++)
            v[u] = __ldcs(&p4[i + u * T]);
        #pragma unroll
        for (int u = 0; u < 8; u++) {
            s0 += __expf(v[u].x);
            s1 += __expf(v[u].y);
            s2 += __expf(v[u].z);
            s3 += __expf(v[u].w);
        }
    }
    for (; i < n4; i += T) {
        float4 v = __ldcs(&p4[i]);
        s0 += __expf(v.x);
        s1 += __expf(v.y);
        s2 += __expf(v.z);
        s3 += __expf(v.w);
    }

    const int done = pro + (n4 << 2);
    const int tail = VOCAB - done;
    if (tid < tail) s1 += __expf(p[done + tid]);

    float s = (s0 + s1) + (s2 + s3);

    // Block reduction (fixed order -> deterministic).
    __shared__ float sm[8];
    #pragma unroll
    for (int o = 16; o > 0; o >>= 1)
        s += __shfl_xor_sync(0xffffffffu, s, o);
    const int wid = tid >> 5;
    const int lid = tid & 31;
    if (lid == 0) sm[wid] = s;
    __syncthreads();

    __shared__ bool is_last;
    if (tid == 0) {
        float v = sm[0] + sm[1] + sm[2] + sm[3] + sm[4] + sm[5] + sm[6] + sm[7];
        const int t = y[row];
        // loss_row = log(sum_j exp(p_j)) - p[y]
        g_row_loss[row] = __logf(v) - p[t];
        __threadfence();
        unsigned int prev = atomicAdd(&g_done, 1u);
        is_last = (prev == (unsigned)(BATCH - 1));
    }
    __syncthreads();

    // Last block to finish reduces all row losses (data fresh in L2).
    if (is_last) {
        float r = 0.f;
        #pragma unroll
        for (int k = 0; k < BATCH / 256; k++)
            r += g_row_loss[tid + k * 256];

        #pragma unroll
        for (int o = 16; o > 0; o >>= 1)
            r += __shfl_xor_sync(0xffffffffu, r, o);
        if (lid == 0) sm[wid] = r;
        __syncthreads();
        if (tid == 0) {
            float tot = sm[0] + sm[1] + sm[2] + sm[3] + sm[4] + sm[5] + sm[6] + sm[7];
            out[0] = tot * (1.0f / BATCH);
            g_done = 0;   // reset for next launch / graph replay
        }
    }
}

extern "C" void kernel_launch(void* const* d_in, const int* in_sizes, int n_in,
                              void* d_out, int out_size)
{
    const float* pred = (const float*)d_in[0];
    const int* y = (const int*)d_in[1];
    float* out = (float*)d_out;

    ce_fused_kernel<<<BATCH, 256>>>(pred, y, out);
}

// round 5
// speedup vs baseline: 1.0314x; 1.0314x over previous
#include <cuda_runtime.h>
#include <cstdint>

#define VOCAB 50257
#define BATCH 4096
#define NBLK  592   // 148 SMs x 4 CTAs -> exactly one persistent wave

// Scratch for per-row losses + completion counter (no device mallocs).
__device__ float g_row_loss[BATCH];
__device__ unsigned int g_done = 0;   // self-resetting each launch

__global__ __launch_bounds__(256, 4) void ce_fused_kernel(
    const float* __restrict__ pred,
    const int* __restrict__ y,       // JAX x64-disabled => int32 labels
    float* __restrict__ out)
{
    const int tid = threadIdx.x;
    const int T = 256;
    const int wid = tid >> 5;
    const int lid = tid & 31;
    __shared__ float sm[8];

    // Persistent loop: each CTA handles rows bid, bid+592, ...
    for (int row = blockIdx.x; row < BATCH; row += NBLK) {
        const float* __restrict__ p = pred + (size_t)row * VOCAB;

        // Row base misalignment (in floats) relative to 16B; prologue to align.
        const int mis = (int)(((uintptr_t)p & 15u) >> 2);
        const int pro = (4 - mis) & 3;

        float s0 = 0.f, s1 = 0.f, s2 = 0.f, s3 = 0.f;

        if (tid < pro) s0 += __expf(p[tid]);

        const float4* __restrict__ p4 = (const float4*)(p + pro);
        const int n4 = (VOCAB - pro) >> 2;

        // Main loop: 8 front-batched streaming LDG.128, then 32 EX2.
        int i = tid;
        for (; i + 7 * T < n4; i += 8 * T) {
            float4 v[8];
            #pragma unroll
            for (int u = 0; u < 8; u++)
                v[u] = __ldcs(&p4[i + u * T]);
            #pragma unroll
            for (int u = 0; u < 8; u++) {
                s0 += __expf(v[u].x);
                s1 += __expf(v[u].y);
                s2 += __expf(v[u].z);
                s3 += __expf(v[u].w);
            }
        }
        for (; i < n4; i += T) {
            float4 v = __ldcs(&p4[i]);
            s0 += __expf(v.x);
            s1 += __expf(v.y);
            s2 += __expf(v.z);
            s3 += __expf(v.w);
        }

        const int done = pro + (n4 << 2);
        const int tail = VOCAB - done;
        if (tid < tail) s1 += __expf(p[done + tid]);

        float s = (s0 + s1) + (s2 + s3);

        // Block reduction (fixed order -> deterministic).
        #pragma unroll
        for (int o = 16; o > 0; o >>= 1)
            s += __shfl_xor_sync(0xffffffffu, s, o);
        if (lid == 0) sm[wid] = s;
        __syncthreads();
        if (tid == 0) {
            float v = sm[0] + sm[1] + sm[2] + sm[3] + sm[4] + sm[5] + sm[6] + sm[7];
            const int t = y[row];
            // loss_row = log(sum_j exp(p_j)) - p[y]
            g_row_loss[row] = __logf(v) - p[t];
        }
        __syncthreads();   // protect sm[] reuse across row iterations
    }

    // CTA finished all its rows: signal, last CTA reduces.
    __shared__ bool is_last;
    if (tid == 0) {
        __threadfence();
        unsigned int prev = atomicAdd(&g_done, 1u);
        is_last = (prev == (unsigned)(NBLK - 1));
    }
    __syncthreads();

    if (is_last) {
        float r = 0.f;
        #pragma unroll
        for (int k = 0; k < BATCH / 256; k++)
            r += g_row_loss[tid + k * 256];

        #pragma unroll
        for (int o = 16; o > 0; o >>= 1)
            r += __shfl_xor_sync(0xffffffffu, r, o);
        if (lid == 0) sm[wid] = r;
        __syncthreads();
        if (tid == 0) {
            float tot = sm[0] + sm[1] + sm[2] + sm[3] + sm[4] + sm[5] + sm[6] + sm[7];
            out[0] = tot * (1.0f / BATCH);
            g_done = 0;   // reset for next launch / graph replay
        }
    }
}

extern "C" void kernel_launch(void* const* d_in, const int* in_sizes, int n_in,
                              void* d_out, int out_size)
{
    const float* pred = (const float*)d_in[0];
    const int* y = (const int*)d_in[1];
    float* out = (float*)d_out;

    ce_fused_kernel<<<NBLK, 256>>>(pred, y, out);
}